// round 9
// baseline (speedup 1.0000x reference)
#include <cuda_runtime.h>
#include <cuda_bf16.h>

// ---------------------------------------------------------------------------
// Quanv3x3 9-qubit statevector sim, packed-f32x2, table-driven constants,
// CRZ-folded init, gate-7 folded into the observable.
//
// One warp per sim (25088 sims). 512 amps = 16 complex/lane, stored as
// 8 x f32x2 packed pairs (pair dimension = qubit 7).
//
// Amp index bits:  lane b0=q8  b1=q5  b2=q3  b3=q1  b4=q2
//                  pair-lo/hi = q7;  k b0=q6  k b1=q4  k b2=q0
//
// CRZ of gates (1,0),(3,2),(8,7),(5,4) folded into init phase (U table).
// Gate 7 (4,0) folded into the measurement:
//   ctrl=1 pairs contribute cosT*(|a|^2-|b|^2)
//                           - 2 sinT [cosF Im(a b*) - sinF Re(a b*)].
// All per-(ch,lane) gate constants precomputed in prep (30 u64 each).
//
// Codegen note (R5/R6 lesson): any launch_bounds tighter than (256,2), or
// 128-thread blocks, poison codegen (+40-60%). Keep (256,2).
// ---------------------------------------------------------------------------

#define FULLMASK 0xffffffffu
typedef unsigned long long u64;

__device__ float g_s[7200];       // sin(pi * avg)  per (b,row,col)
__device__ float g_c[7200];       // cos(pi * avg)
__device__ u64   g_tab[4 * 32 * 30];  // per-(ch,lane) gate constants
__device__ u64   g_utab[4 * 32 * 8];  // per-(ch,lane) folded-U: Ure[4],Uim[4]
__device__ float g_w[12];             // per-ch: w0=cosT, w1=2 sinT cosF, w2=2 sinT sinF

// ---- packed f32x2 primitives ----------------------------------------------
__device__ __forceinline__ u64 pk(float lo, float hi) {
    u64 r;
    asm("mov.b64 %0, {%1, %2};" : "=l"(r) : "f"(lo), "f"(hi));
    return r;
}
__device__ __forceinline__ void upk(u64 v, float& lo, float& hi) {
    asm("mov.b64 {%0, %1}, %2;" : "=f"(lo), "=f"(hi) : "l"(v));
}
__device__ __forceinline__ u64 f2fma(u64 a, u64 b, u64 c) {
    u64 d;
    asm("fma.rn.f32x2 %0, %1, %2, %3;" : "=l"(d) : "l"(a), "l"(b), "l"(c));
    return d;
}
__device__ __forceinline__ u64 f2mul(u64 a, u64 b) {
    u64 d;
    asm("mul.rn.f32x2 %0, %1, %2;" : "=l"(d) : "l"(a), "l"(b));
    return d;
}
__device__ __forceinline__ u64 f2swap(u64 v) {
    float lo, hi; upk(v, lo, hi); return pk(hi, lo);
}

__global__ void prep_kernel(const float* __restrict__ x,
                            const float* __restrict__ qp,
                            float* __restrict__ out) {
    int i = blockIdx.x * blockDim.x + threadIdx.x;
    if (i < 28800) out[i] = 0.0f;
    if (i < 7200) {
        const float* p = x + i * 3;
        float a = (p[0] + p[1] + p[2]) * (1.0f / 3.0f);
        float sv, cv;
        sincosf(3.14159265358979323846f * a, &sv, &cv);
        g_s[i] = sv;
        g_c[i] = cv;
    }
    if (i < 128) {
        int ch = i >> 5, lane = i & 31;
        const float* th = qp + ch * 16;
        float hc[16], hs[16];
#pragma unroll
        for (int j = 0; j < 16; j++) sincosf(th[j] * 0.5f, &hs[j], &hc[j]);

        u64* tab = g_tab + (ch * 32 + lane) * 30;
        // g0 CRX (th[1]), ctl = lane&8
        {
            bool t = (lane & 8); float cx = t ? hc[1] : 1.f, sx = t ? hs[1] : 0.f;
            tab[0] = pk(cx, cx); tab[1] = pk(sx, sx); tab[2] = pk(-sx, -sx);
        }
        // g1 CRX (th[3]), ctl = lane&4
        {
            bool t = (lane & 4); float cx = t ? hc[3] : 1.f, sx = t ? hs[3] : 0.f;
            tab[3] = pk(cx, cx); tab[4] = pk(sx, sx); tab[5] = pk(-sx, -sx);
        }
        // g2 CRZ (th[4]) + CRX (th[5]), ctl = lane&16
        {
            bool t = (lane & 16);
            float cz = t ? hc[4] : 1.f, sz = t ? hs[4] : 0.f;
            tab[6] = pk(cz, cz); tab[7] = pk(sz, sz); tab[8] = pk(-sz, -sz);
            float cx = t ? hc[5] : 1.f, sx = t ? hs[5] : 0.f;
            tab[9] = pk(cx, cx); tab[10] = pk(sx, sx); tab[11] = pk(-sx, -sx);
        }
        // g3 CRX (th[7]), ctl = lane&1
        {
            bool t = (lane & 1); float cx = t ? hc[7] : 1.f, sx = t ? hs[7] : 0.f;
            tab[12] = pk(cx, cx); tab[13] = pk(sx, sx); tab[14] = pk(-sx, -sx);
        }
        // g4 CRX (th[9]), ctl = lane&2
        {
            bool t = (lane & 2); float cx = t ? hc[9] : 1.f, sx = t ? hs[9] : 0.f;
            tab[15] = pk(cx, cx); tab[16] = pk(sx, sx); tab[17] = pk(-sx, -sx);
        }
        // g5 CRZ (th[10]) + CRX (th[11]), ctrl = pair-hi slot
        {
            float c = hc[10], s = hs[10];
            tab[18] = pk(1.f, c); tab[19] = pk(0.f, s); tab[20] = pk(0.f, -s);
            float cx = hc[11], sx = hs[11];
            tab[21] = pk(1.f, cx); tab[22] = pk(0.f, sx); tab[23] = pk(0.f, -sx);
        }
        // g6 CRZ (th[12]) + CRX (th[13]), ctrl = k bit0
        {
            float c = hc[12], s = hs[12];
            tab[24] = pk(c, c); tab[25] = pk(s, s); tab[26] = pk(-s, -s);
            float cx = hc[13], sx = hs[13];
            tab[27] = pk(cx, cx); tab[28] = pk(sx, sx); tab[29] = pk(-sx, -sx);
        }

        // ---- folded-U table (CRZ of g0,g1,g3,g4 + global (-i)^popc) ------
        {
            float c0 = hc[0], s0 = hs[0];     // g0 CRZ(1,0)
            float c2g = hc[2], s2g = hs[2];   // g1 CRZ(3,2)
            float c6g = hc[6], s6g = hs[6];   // g3 CRZ(8,7)
            float c8g = hc[8], s8g = hs[8];   // g4 CRZ(5,4)

            int lk = __popc(lane & 31) & 3;
            float wr = (lk == 0) ? 1.0f : ((lk == 2) ? -1.0f : 0.0f);
            float wi = (lk == 3) ? 1.0f : ((lk == 1) ? -1.0f : 0.0f);

            bool aCtl = (lane & 4) != 0;
            float pAr = aCtl ? c2g : 1.0f;
            float pAi = aCtl ? ((lane & 16) ? s2g : -s2g) : 0.0f;
            float wpr = wr * pAr - wi * pAi;
            float wpi = wr * pAi + wi * pAr;

            bool g3c_ = (lane & 1) != 0;
            float e3c = g3c_ ? c6g : 1.0f, e3s = g3c_ ? s6g : 0.0f;
            u64 Sre = pk(e3c, e3s);
            u64 Sim = pk(-e3s, -e3c);

            u64 wpr2 = pk(wpr, wpr), wpi2 = pk(wpi, wpi), nwpi2 = pk(-wpi, -wpi);
            u64 Tre = f2fma(wpr2, Sre, f2mul(nwpi2, Sim));
            u64 Tim = f2fma(wpr2, Sim, f2mul(wpi2, Sre));

            bool g4c_ = (lane & 2) != 0;
            float e4c = g4c_ ? c8g : 1.0f, e4s = g4c_ ? s8g : 0.0f;
            float q2r[2] = { e4c,  e4s };
            float q2i[2] = { -e4s, -e4c };
            bool g0c_ = (lane & 8) != 0;
            float e0c = g0c_ ? c0 : 1.0f, e0s = g0c_ ? s0 : 0.0f;
            float q4r[2] = { e0c,  e0s };
            float q4i[2] = { -e0s, -e0c };

            u64* ut = g_utab + (ch * 32 + lane) * 8;
#pragma unroll
            for (int i4 = 0; i4 < 2; i4++) {
#pragma unroll
                for (int i2 = 0; i2 < 2; i2++) {
                    float qr = q2r[i2] * q4r[i4] - q2i[i2] * q4i[i4];
                    float qi = q2r[i2] * q4i[i4] + q2i[i2] * q4r[i4];
                    u64 qr2 = pk(qr, qr), qi2 = pk(qi, qi), nqi2 = pk(-qi, -qi);
                    ut[i2 + 2 * i4]     = f2fma(qr2, Tre, f2mul(nqi2, Tim));
                    ut[4 + i2 + 2 * i4] = f2fma(qr2, Tim, f2mul(qi2, Tre));
                }
            }
        }

        // ---- measurement fold weights (per channel) -----------------------
        if (lane == 0) {
            float s15, c15, s14, c14;
            sincosf(th[15], &s15, &c15);
            sincosf(th[14], &s14, &c14);
            g_w[ch * 3 + 0] = c15;
            g_w[ch * 3 + 1] = 2.0f * s15 * c14;
            g_w[ch * 3 + 2] = 2.0f * s15 * s14;
        }
    }
}

// CRZ on one packed pair: nr = ch*r + (-se)*i ; ni = ch*i + se*r
__device__ __forceinline__ void crz1(u64& r, u64& i, u64 ch2, u64 se2, u64 mse2) {
    u64 tr = f2mul(mse2, i);
    u64 ti = f2mul(se2, r);
    r = f2fma(ch2, r, tr);
    i = f2fma(ch2, i, ti);
}

// CRX mixing packed pair A (target bit 0) with packed pair B (target bit 1).
__device__ __forceinline__ void crx2(u64& rA, u64& iA, u64& rB, u64& iB,
                                     u64 ch2, u64 sh2, u64 msh2) {
    u64 m0 = f2mul(sh2,  iB);
    u64 m1 = f2mul(msh2, rB);
    u64 m2 = f2mul(sh2,  iA);
    u64 m3 = f2mul(msh2, rA);
    rA = f2fma(ch2, rA, m0);
    iA = f2fma(ch2, iA, m1);
    rB = f2fma(ch2, rB, m2);
    iB = f2fma(ch2, iB, m3);
}

__global__ __launch_bounds__(256, 2) void sim_kernel(float* __restrict__ out) {
    int gwarp = (blockIdx.x * blockDim.x + threadIdx.x) >> 5;
    int lane = threadIdx.x & 31;

    int b   = gwarp / 3136;
    int rem = gwarp - b * 3136;
    int ch  = rem / 784;
    int pos = rem - ch * 784;
    int r_  = pos / 28;
    int c_  = pos - r_ * 28;

    // ---- patch angles: cq = sin(pi*p), sq = -cos(pi*p)
    float sv = 0.0f, cv = 0.0f;
    if (lane < 9) {
        int dr = lane / 3;
        int dc = lane - dr * 3;
        int idx = b * 900 + (r_ + dr) * 30 + (c_ + dc);
        sv = __ldg(g_s + idx);
        cv = __ldg(g_c + idx);
    }
    float cq[9], sq[9];
#pragma unroll
    for (int q = 0; q < 9; q++) {
        cq[q] = __shfl_sync(FULLMASK, sv, q);
        sq[q] = -__shfl_sync(FULLMASK, cv, q);
    }

    const u64* tab = g_tab + (ch * 32 + lane) * 30;
    const u64* ut  = g_utab + (ch * 32 + lane) * 8;

    // ---- folded-U phases from table
    u64 Ure[4], Uim[4];
#pragma unroll
    for (int j = 0; j < 4; j++) {
        Ure[j] = __ldg(ut + j);
        Uim[j] = __ldg(ut + 4 + j);
    }

    // ---- initial state with folded phases
    float lr = ((lane & 1)  ? sq[8] : cq[8]) *
               ((lane & 2)  ? sq[5] : cq[5]) *
               ((lane & 4)  ? sq[3] : cq[3]) *
               ((lane & 8)  ? sq[1] : cq[1]) *
               ((lane & 16) ? sq[2] : cq[2]);
    u64 cs7  = pk(cq[7], sq[7]);
    u64 ncs7 = pk(-cq[7], -sq[7]);

    u64 re[8], im[8];
#pragma unroll
    for (int k = 0; k < 8; k++) {
        float rr = lr * ((k & 1) ? sq[6] : cq[6]) *
                        ((k & 2) ? sq[4] : cq[4]) *
                        ((k & 4) ? sq[0] : cq[0]);
        u64 rr2 = pk(rr, rr);
        int idx = ((k >> 1) & 1) + 2 * ((k >> 2) & 1);
        if (!(k & 1)) {
            u64 R2 = f2mul(rr2, cs7);
            re[k] = f2mul(R2, Ure[idx]);
            im[k] = f2mul(R2, Uim[idx]);
        } else {
            u64 R2  = f2mul(rr2, cs7);
            u64 Rn2 = f2mul(rr2, ncs7);
            re[k] = f2mul(R2,  Uim[idx]);
            im[k] = f2mul(Rn2, Ure[idx]);
        }
    }

    // ---- gate 0: (1,0) CRX. pairs k^4
    {
        u64 cx2 = __ldg(tab + 0), x2P = __ldg(tab + 1), x2N = __ldg(tab + 2);
        crx2(re[0], im[0], re[4], im[4], cx2, x2P, x2N);
        crx2(re[1], im[1], re[5], im[5], cx2, x2P, x2N);
        crx2(re[2], im[2], re[6], im[6], cx2, x2P, x2N);
        crx2(re[3], im[3], re[7], im[7], cx2, x2P, x2N);
    }
    // ---- gate 1: (3,2) CRX, cross-lane xor16
    {
        u64 cx2 = __ldg(tab + 3), x2P = __ldg(tab + 4), x2N = __ldg(tab + 5);
#pragma unroll
        for (int k = 0; k < 8; k++) {
            u64 orr = __shfl_xor_sync(FULLMASK, re[k], 16);
            u64 oii = __shfl_xor_sync(FULLMASK, im[k], 16);
            u64 m0 = f2mul(x2P, oii);
            u64 m1 = f2mul(x2N, orr);
            re[k] = f2fma(cx2, re[k], m0);
            im[k] = f2fma(cx2, im[k], m1);
        }
    }
    // ---- gate 2: (2,0) CRZ + CRX. CRZ sign by k&4; CRX pairs k^4
    {
        u64 ch2 = __ldg(tab + 6), sP = __ldg(tab + 7), sN = __ldg(tab + 8);
#pragma unroll
        for (int k = 0; k < 8; k++)
            crz1(re[k], im[k], ch2, (k & 4) ? sP : sN, (k & 4) ? sN : sP);
        u64 cx2 = __ldg(tab + 9), x2P = __ldg(tab + 10), x2N = __ldg(tab + 11);
        crx2(re[0], im[0], re[4], im[4], cx2, x2P, x2N);
        crx2(re[1], im[1], re[5], im[5], cx2, x2P, x2N);
        crx2(re[2], im[2], re[6], im[6], cx2, x2P, x2N);
        crx2(re[3], im[3], re[7], im[7], cx2, x2P, x2N);
    }
    // ---- gate 3: (8,7) CRX, target = within-pair bit
    {
        u64 cx2 = __ldg(tab + 12), x2P = __ldg(tab + 13), x2N = __ldg(tab + 14);
#pragma unroll
        for (int k = 0; k < 8; k++) {
            u64 swi = f2swap(im[k]);
            u64 swr = f2swap(re[k]);
            u64 m0 = f2mul(x2P, swi);
            u64 m1 = f2mul(x2N, swr);
            re[k] = f2fma(cx2, re[k], m0);
            im[k] = f2fma(cx2, im[k], m1);
        }
    }
    // ---- gate 4: (5,4) CRX. pairs k^2
    {
        u64 cx2 = __ldg(tab + 15), x2P = __ldg(tab + 16), x2N = __ldg(tab + 17);
        crx2(re[0], im[0], re[2], im[2], cx2, x2P, x2N);
        crx2(re[1], im[1], re[3], im[3], cx2, x2P, x2N);
        crx2(re[4], im[4], re[6], im[6], cx2, x2P, x2N);
        crx2(re[5], im[5], re[7], im[7], cx2, x2P, x2N);
    }
    // ---- gate 5: (7,6) CRZ + CRX. ctrl = pair-hi; tgt = k bit0
    {
        u64 ch2 = __ldg(tab + 18), sP = __ldg(tab + 19), sN = __ldg(tab + 20);
#pragma unroll
        for (int k = 0; k < 8; k++)
            crz1(re[k], im[k], ch2, (k & 1) ? sP : sN, (k & 1) ? sN : sP);
        u64 cx2 = __ldg(tab + 21), x2P = __ldg(tab + 22), x2N = __ldg(tab + 23);
        crx2(re[0], im[0], re[1], im[1], cx2, x2P, x2N);
        crx2(re[2], im[2], re[3], im[3], cx2, x2P, x2N);
        crx2(re[4], im[4], re[5], im[5], cx2, x2P, x2N);
        crx2(re[6], im[6], re[7], im[7], cx2, x2P, x2N);
    }
    // ---- gate 6: (6,4) CRZ + CRX. ctl = k&1; tgt = k bit1; sign by k&2
    {
        u64 ch2 = __ldg(tab + 24), sP = __ldg(tab + 25), sN = __ldg(tab + 26);
        crz1(re[1], im[1], ch2, sN, sP);
        crz1(re[3], im[3], ch2, sP, sN);
        crz1(re[5], im[5], ch2, sN, sP);
        crz1(re[7], im[7], ch2, sP, sN);
        u64 cx2 = __ldg(tab + 27), x2P = __ldg(tab + 28), x2N = __ldg(tab + 29);
        crx2(re[1], im[1], re[3], im[3], cx2, x2P, x2N);
        crx2(re[5], im[5], re[7], im[7], cx2, x2P, x2N);
    }

    // ---- gate 7 folded into the observable --------------------------------
    // ctrl=0 (k in {0,1} vs {4,5}): plain |.|^2 difference.
    // ctrl=1 (k in {2,3} vs {6,7}): cosT*dZ - w1*Im(ab*) + w2*Re(ab*).
    u64 aP = 0ULL, aN = 0ULL, dP = 0ULL, dN = 0ULL;
    u64 rp = 0ULL, ip = 0ULL, in_ = 0ULL;
    aP = f2fma(re[0], re[0], aP); aP = f2fma(im[0], im[0], aP);
    aP = f2fma(re[1], re[1], aP); aP = f2fma(im[1], im[1], aP);
    aN = f2fma(re[4], re[4], aN); aN = f2fma(im[4], im[4], aN);
    aN = f2fma(re[5], re[5], aN); aN = f2fma(im[5], im[5], aN);
    dP = f2fma(re[2], re[2], dP); dP = f2fma(im[2], im[2], dP);
    dP = f2fma(re[3], re[3], dP); dP = f2fma(im[3], im[3], dP);
    dN = f2fma(re[6], re[6], dN); dN = f2fma(im[6], im[6], dN);
    dN = f2fma(re[7], re[7], dN); dN = f2fma(im[7], im[7], dN);
    rp = f2fma(re[2], re[6], rp); rp = f2fma(im[2], im[6], rp);
    rp = f2fma(re[3], re[7], rp); rp = f2fma(im[3], im[7], rp);
    ip = f2fma(im[2], re[6], ip); ip = f2fma(im[3], re[7], ip);
    in_ = f2fma(re[2], im[6], in_); in_ = f2fma(re[3], im[7], in_);

    float w0 = __ldg(g_w + ch * 3 + 0);
    float w1 = __ldg(g_w + ch * 3 + 1);
    float w2 = __ldg(g_w + ch * 3 + 2);

    float l, h;
    upk(aP, l, h);  float A0 = l + h;
    upk(aN, l, h);  float A1 = l + h;
    upk(dP, l, h);  float D0 = l + h;
    upk(dN, l, h);  float D1 = l + h;
    upk(rp, l, h);  float RP = l + h;
    upk(ip, l, h);  float IP = l + h;
    upk(in_, l, h); float IN = l + h;

    float z = (A0 - A1) + w0 * (D0 - D1) - w1 * (IP - IN) + w2 * RP;
#pragma unroll
    for (int o = 16; o > 0; o >>= 1)
        z += __shfl_xor_sync(FULLMASK, z, o);

    if (lane == 0) {
        out[((b * 30 + r_ + 1) * 30 + (c_ + 1)) * 4 + ch] = (z + 1.0f) * 0.5f;
    }
}

extern "C" void kernel_launch(void* const* d_in, const int* in_sizes, int n_in,
                              void* d_out, int out_size) {
    const float* x  = (const float*)d_in[0];
    const float* qp = (const float*)d_in[1];
    if (n_in >= 2 && in_sizes[0] == 64) {
        const float* t = x; x = qp; qp = t;
    }
    float* out = (float*)d_out;

    prep_kernel<<<(28800 + 255) / 256, 256>>>(x, qp, out);
    sim_kernel<<<3136, 256>>>(out);
}

// round 10
// speedup vs baseline: 1.5794x; 1.5794x over previous
#include <cuda_runtime.h>
#include <cuda_bf16.h>

// ---------------------------------------------------------------------------
// Quanv3x3 9-qubit statevector sim, packed-f32x2, CRZ-folded init,
// gate-7 folded into the observable. In-register constants (R8 lesson:
// per-lane constant tables cost more in L1 latency than ~5 ALU ops of
// recomputation; only warp-uniform 32-bit loads are free).
//
// One warp per sim (25088 sims). 512 amps = 16 complex/lane, stored as
// 8 x f32x2 packed pairs (pair dimension = qubit 7).
//
// Amp index bits:  lane b0=q8  b1=q5  b2=q3  b3=q1  b4=q2
//                  pair-lo/hi = q7;  k b0=q6  k b1=q4  k b2=q0
//
// CRZ of gates (1,0),(3,2),(8,7),(5,4) folded into init phase.
// Gate 7 (4,0) folded into measurement: on ctrl=1 pairs (a=k{2,3}, b=k{6,7})
//   contribution = cosT*(|a|^2-|b|^2) - 2 sinT [cosF Im(a b*) - sinF Re(a b*)].
//
// Codegen note (R5/R6): launch_bounds tighter than (256,2) or 128-thread
// blocks poison codegen (+40-60%). Keep (256,2).
// ---------------------------------------------------------------------------

#define FULLMASK 0xffffffffu
typedef unsigned long long u64;

__device__ float g_s[7200];     // sin(pi * avg)  per (b,row,col)
__device__ float g_c[7200];     // cos(pi * avg)
__device__ float g_gc[64];      // cos(theta/2) per channel (4x16)
__device__ float g_gs[64];      // sin(theta/2)
__device__ float g_w[12];       // per-ch: cosT, 2 sinT cosF, 2 sinT sinF

__global__ void prep_kernel(const float* __restrict__ x,
                            const float* __restrict__ qp,
                            float* __restrict__ out) {
    int i = blockIdx.x * blockDim.x + threadIdx.x;
    if (i < 28800) out[i] = 0.0f;
    if (i < 7200) {
        const float* p = x + i * 3;
        float a = (p[0] + p[1] + p[2]) * (1.0f / 3.0f);
        float sv, cv;
        sincosf(3.14159265358979323846f * a, &sv, &cv);
        g_s[i] = sv;
        g_c[i] = cv;
    }
    if (i < 64) {
        float h = qp[i] * 0.5f;
        g_gc[i] = cosf(h);
        g_gs[i] = sinf(h);
    }
    if (i < 4) {
        const float* th = qp + i * 16;
        float s15, c15, s14, c14;
        sincosf(th[15], &s15, &c15);   // gate 7 CRX angle (full)
        sincosf(th[14], &s14, &c14);   // gate 7 CRZ angle (full)
        g_w[i * 3 + 0] = c15;
        g_w[i * 3 + 1] = 2.0f * s15 * c14;
        g_w[i * 3 + 2] = 2.0f * s15 * s14;
    }
}

// ---- packed f32x2 primitives ----------------------------------------------
__device__ __forceinline__ u64 pk(float lo, float hi) {
    u64 r;
    asm("mov.b64 %0, {%1, %2};" : "=l"(r) : "f"(lo), "f"(hi));
    return r;
}
__device__ __forceinline__ void upk(u64 v, float& lo, float& hi) {
    asm("mov.b64 {%0, %1}, %2;" : "=f"(lo), "=f"(hi) : "l"(v));
}
__device__ __forceinline__ u64 f2fma(u64 a, u64 b, u64 c) {
    u64 d;
    asm("fma.rn.f32x2 %0, %1, %2, %3;" : "=l"(d) : "l"(a), "l"(b), "l"(c));
    return d;
}
__device__ __forceinline__ u64 f2mul(u64 a, u64 b) {
    u64 d;
    asm("mul.rn.f32x2 %0, %1, %2;" : "=l"(d) : "l"(a), "l"(b));
    return d;
}
__device__ __forceinline__ u64 f2swap(u64 v) {
    float lo, hi; upk(v, lo, hi); return pk(hi, lo);
}

// CRZ on one packed pair: nr = ch*r + (-se)*i ; ni = ch*i + se*r
__device__ __forceinline__ void crz1(u64& r, u64& i, u64 ch2, u64 se2, u64 mse2) {
    u64 tr = f2mul(mse2, i);
    u64 ti = f2mul(se2, r);
    r = f2fma(ch2, r, tr);
    i = f2fma(ch2, i, ti);
}

// CRX mixing packed pair A (target bit 0) with packed pair B (target bit 1).
__device__ __forceinline__ void crx2(u64& rA, u64& iA, u64& rB, u64& iB,
                                     u64 ch2, u64 sh2, u64 msh2) {
    u64 m0 = f2mul(sh2,  iB);
    u64 m1 = f2mul(msh2, rB);
    u64 m2 = f2mul(sh2,  iA);
    u64 m3 = f2mul(msh2, rA);
    rA = f2fma(ch2, rA, m0);
    iA = f2fma(ch2, iA, m1);
    rB = f2fma(ch2, rB, m2);
    iB = f2fma(ch2, iB, m3);
}

__global__ __launch_bounds__(256, 2) void sim_kernel(float* __restrict__ out) {
    int gwarp = (blockIdx.x * blockDim.x + threadIdx.x) >> 5;
    int lane = threadIdx.x & 31;

    int b   = gwarp / 3136;
    int rem = gwarp - b * 3136;
    int ch  = rem / 784;
    int pos = rem - ch * 784;
    int r_  = pos / 28;
    int c_  = pos - r_ * 28;

    // ---- patch angles: cq = sin(pi*p), sq = -cos(pi*p)
    float sv = 0.0f, cv = 0.0f;
    if (lane < 9) {
        int dr = lane / 3;
        int dc = lane - dr * 3;
        int idx = b * 900 + (r_ + dr) * 30 + (c_ + dc);
        sv = __ldg(g_s + idx);
        cv = __ldg(g_c + idx);
    }
    float cq[9], sq[9];
#pragma unroll
    for (int q = 0; q < 9; q++) {
        cq[q] = __shfl_sync(FULLMASK, sv, q);
        sq[q] = -__shfl_sync(FULLMASK, cv, q);
    }

    const float* gc = g_gc + ch * 16;
    const float* gs = g_gs + ch * 16;

    // ---- folded CRZ phases (gates g0, g1, g3, g4) -------------------------
    float c0 = __ldg(gc + 0), s0 = __ldg(gs + 0);   // g0 CRZ(1,0)
    float c2g = __ldg(gc + 2), s2g = __ldg(gs + 2); // g1 CRZ(3,2)
    float c6g = __ldg(gc + 6), s6g = __ldg(gs + 6); // g3 CRZ(8,7)
    float c8g = __ldg(gc + 8), s8g = __ldg(gs + 8); // g4 CRZ(5,4)

    // w = (-i)^popc(lane)
    int lk = __popc(lane & 31) & 3;
    float wr = (lk == 0) ? 1.0f : ((lk == 2) ? -1.0f : 0.0f);
    float wi = (lk == 3) ? 1.0f : ((lk == 1) ? -1.0f : 0.0f);

    // pA: g1 CRZ, ctrl=lane&4, tgt=lane&16 (pure lane phase)
    bool aCtl = (lane & 4) != 0;
    float pAr = aCtl ? c2g : 1.0f;
    float pAi = aCtl ? ((lane & 16) ? s2g : -s2g) : 0.0f;
    float wpr = wr * pAr - wi * pAi;   // w' = w * pA
    float wpi = wr * pAi + wi * pAr;

    // S (packed over slot): g3 CRZ (ctrl=lane&1, tgt=slot) * (-i)^slot
    bool g3c_ = (lane & 1) != 0;
    float e3c = g3c_ ? c6g : 1.0f, e3s = g3c_ ? s6g : 0.0f;
    u64 Sre = pk(e3c, e3s);
    u64 Sim = pk(-e3s, -e3c);

    // T = w' * S
    u64 wpr2 = pk(wpr, wpr), wpi2 = pk(wpi, wpi), nwpi2 = pk(-wpi, -wpi);
    u64 Tre = f2fma(wpr2, Sre, f2mul(nwpi2, Sim));
    u64 Tim = f2fma(wpr2, Sim, f2mul(wpi2, Sre));

    // qq2 (k bit1 / q4, gate g4) and qq4 (k bit2 / q0, gate g0)
    bool g4c_ = (lane & 2) != 0;
    float e4c = g4c_ ? c8g : 1.0f, e4s = g4c_ ? s8g : 0.0f;
    float q2r[2] = { e4c,  e4s };
    float q2i[2] = { -e4s, -e4c };
    bool g0c_ = (lane & 8) != 0;
    float e0c = g0c_ ? c0 : 1.0f, e0s = g0c_ ? s0 : 0.0f;
    float q4r[2] = { e0c,  e0s };
    float q4i[2] = { -e0s, -e0c };

    // U[idx] = T * (qq2*qq4), idx = k2bit + 2*k4bit
    u64 Ure[4], Uim[4];
#pragma unroll
    for (int i4 = 0; i4 < 2; i4++) {
#pragma unroll
        for (int i2 = 0; i2 < 2; i2++) {
            float qr = q2r[i2] * q4r[i4] - q2i[i2] * q4i[i4];
            float qi = q2r[i2] * q4i[i4] + q2i[i2] * q4r[i4];
            u64 qr2 = pk(qr, qr), qi2 = pk(qi, qi), nqi2 = pk(-qi, -qi);
            Ure[i2 + 2 * i4] = f2fma(qr2, Tre, f2mul(nqi2, Tim));
            Uim[i2 + 2 * i4] = f2fma(qr2, Tim, f2mul(qi2, Tre));
        }
    }

    // ---- initial state with folded phases ---------------------------------
    float lr = ((lane & 1)  ? sq[8] : cq[8]) *
               ((lane & 2)  ? sq[5] : cq[5]) *
               ((lane & 4)  ? sq[3] : cq[3]) *
               ((lane & 8)  ? sq[1] : cq[1]) *
               ((lane & 16) ? sq[2] : cq[2]);
    u64 cs7  = pk(cq[7], sq[7]);
    u64 ncs7 = pk(-cq[7], -sq[7]);

    u64 re[8], im[8];
#pragma unroll
    for (int k = 0; k < 8; k++) {
        float rr = lr * ((k & 1) ? sq[6] : cq[6]) *
                        ((k & 2) ? sq[4] : cq[4]) *
                        ((k & 4) ? sq[0] : cq[0]);
        u64 rr2 = pk(rr, rr);
        int idx = ((k >> 1) & 1) + 2 * ((k >> 2) & 1);
        if (!(k & 1)) {
            u64 R2 = f2mul(rr2, cs7);
            re[k] = f2mul(R2, Ure[idx]);
            im[k] = f2mul(R2, Uim[idx]);
        } else {
            // extra (-i) for k bit0: (re,im) <- (im, -re) of the even formula
            u64 R2  = f2mul(rr2, cs7);
            u64 Rn2 = f2mul(rr2, ncs7);
            re[k] = f2mul(R2,  Uim[idx]);
            im[k] = f2mul(Rn2, Ure[idx]);
        }
    }

    // ---- gate 0: (1,0) CRX only. ctl = lane&8; pairs k^4
    {
        bool ctl = (lane & 8) != 0;
        float cx = __ldg(gc + 1), sx = __ldg(gs + 1);
        float cxe = ctl ? cx : 1.0f, sxe = ctl ? sx : 0.0f;
        u64 cx2 = pk(cxe, cxe), x2P = pk(sxe, sxe), x2N = pk(-sxe, -sxe);
        crx2(re[0], im[0], re[4], im[4], cx2, x2P, x2N);
        crx2(re[1], im[1], re[5], im[5], cx2, x2P, x2N);
        crx2(re[2], im[2], re[6], im[6], cx2, x2P, x2N);
        crx2(re[3], im[3], re[7], im[7], cx2, x2P, x2N);
    }
    // ---- gate 1: (3,2) CRX only. ctl = lane&4; cross-lane xor16
    {
        bool ctl = (lane & 4) != 0;
        float cx = __ldg(gc + 3), sx = __ldg(gs + 3);
        float cxe = ctl ? cx : 1.0f, sxe = ctl ? sx : 0.0f;
        u64 cx2 = pk(cxe, cxe), x2P = pk(sxe, sxe), x2N = pk(-sxe, -sxe);
#pragma unroll
        for (int k = 0; k < 8; k++) {
            u64 orr = __shfl_xor_sync(FULLMASK, re[k], 16);
            u64 oii = __shfl_xor_sync(FULLMASK, im[k], 16);
            u64 m0 = f2mul(x2P, oii);
            u64 m1 = f2mul(x2N, orr);
            re[k] = f2fma(cx2, re[k], m0);
            im[k] = f2fma(cx2, im[k], m1);
        }
    }
    // ---- gate 2: (2,0) CRZ + CRX. ctl = lane&16; CRZ sign by k&4; pairs k^4
    {
        bool ctl = (lane & 16) != 0;
        float c = __ldg(gc + 4), s = __ldg(gs + 4);
        float ce = ctl ? c : 1.0f, se = ctl ? s : 0.0f;
        u64 ch2 = pk(ce, ce), sP = pk(se, se), sN = pk(-se, -se);
#pragma unroll
        for (int k = 0; k < 8; k++)
            crz1(re[k], im[k], ch2, (k & 4) ? sP : sN, (k & 4) ? sN : sP);
        float cx = __ldg(gc + 5), sx = __ldg(gs + 5);
        float cxe = ctl ? cx : 1.0f, sxe = ctl ? sx : 0.0f;
        u64 cx2 = pk(cxe, cxe), x2P = pk(sxe, sxe), x2N = pk(-sxe, -sxe);
        crx2(re[0], im[0], re[4], im[4], cx2, x2P, x2N);
        crx2(re[1], im[1], re[5], im[5], cx2, x2P, x2N);
        crx2(re[2], im[2], re[6], im[6], cx2, x2P, x2N);
        crx2(re[3], im[3], re[7], im[7], cx2, x2P, x2N);
    }
    // ---- gate 3: (8,7) CRX only. ctl = lane&1; tgt = within-pair bit
    {
        bool ctl = (lane & 1) != 0;
        float cx = __ldg(gc + 7), sx = __ldg(gs + 7);
        float cxe = ctl ? cx : 1.0f, sxe = ctl ? sx : 0.0f;
        u64 cx2 = pk(cxe, cxe), x2P = pk(sxe, sxe), x2N = pk(-sxe, -sxe);
#pragma unroll
        for (int k = 0; k < 8; k++) {
            u64 swi = f2swap(im[k]);
            u64 swr = f2swap(re[k]);
            u64 m0 = f2mul(x2P, swi);
            u64 m1 = f2mul(x2N, swr);
            re[k] = f2fma(cx2, re[k], m0);
            im[k] = f2fma(cx2, im[k], m1);
        }
    }
    // ---- gate 4: (5,4) CRX only. ctl = lane&2; pairs k^2
    {
        bool ctl = (lane & 2) != 0;
        float cx = __ldg(gc + 9), sx = __ldg(gs + 9);
        float cxe = ctl ? cx : 1.0f, sxe = ctl ? sx : 0.0f;
        u64 cx2 = pk(cxe, cxe), x2P = pk(sxe, sxe), x2N = pk(-sxe, -sxe);
        crx2(re[0], im[0], re[2], im[2], cx2, x2P, x2N);
        crx2(re[1], im[1], re[3], im[3], cx2, x2P, x2N);
        crx2(re[4], im[4], re[6], im[6], cx2, x2P, x2N);
        crx2(re[5], im[5], re[7], im[7], cx2, x2P, x2N);
    }
    // ---- gate 5: (7,6) CRZ + CRX. ctrl = pair-hi (q7); tgt = k bit0 (q6)
    {
        float c = __ldg(gc + 10), s = __ldg(gs + 10);
        u64 ch2 = pk(1.0f, c), sP = pk(0.0f, s), sN = pk(0.0f, -s);
#pragma unroll
        for (int k = 0; k < 8; k++)
            crz1(re[k], im[k], ch2, (k & 1) ? sP : sN, (k & 1) ? sN : sP);
        float cx = __ldg(gc + 11), sx = __ldg(gs + 11);
        u64 cx2 = pk(1.0f, cx), x2P = pk(0.0f, sx), x2N = pk(0.0f, -sx);
        crx2(re[0], im[0], re[1], im[1], cx2, x2P, x2N);
        crx2(re[2], im[2], re[3], im[3], cx2, x2P, x2N);
        crx2(re[4], im[4], re[5], im[5], cx2, x2P, x2N);
        crx2(re[6], im[6], re[7], im[7], cx2, x2P, x2N);
    }
    // ---- gate 6: (6,4) CRZ + CRX. ctl = k&1 (q6); tgt = k bit1 (q4)
    {
        float c = __ldg(gc + 12), s = __ldg(gs + 12);
        u64 ch2 = pk(c, c), sP = pk(s, s), sN = pk(-s, -s);
        crz1(re[1], im[1], ch2, sN, sP);
        crz1(re[3], im[3], ch2, sP, sN);
        crz1(re[5], im[5], ch2, sN, sP);
        crz1(re[7], im[7], ch2, sP, sN);
        float cx = __ldg(gc + 13), sx = __ldg(gs + 13);
        u64 cx2 = pk(cx, cx), x2P = pk(sx, sx), x2N = pk(-sx, -sx);
        crx2(re[1], im[1], re[3], im[3], cx2, x2P, x2N);
        crx2(re[5], im[5], re[7], im[7], cx2, x2P, x2N);
    }

    // ---- gate 7 (4,0) folded into the observable --------------------------
    // ctrl=0 pairs (k 0,1 vs 4,5): plain |.|^2 difference.
    // ctrl=1 pairs (a = k 2,3; b = k 6,7):
    //   cosT*(|a|^2-|b|^2) - w1*Im(a b*) + w2*Re(a b*)
    u64 aP = 0ULL, aN = 0ULL, dP = 0ULL, dN = 0ULL;
    u64 rp = 0ULL, ip = 0ULL, in_ = 0ULL;
    aP = f2fma(re[0], re[0], aP); aP = f2fma(im[0], im[0], aP);
    aP = f2fma(re[1], re[1], aP); aP = f2fma(im[1], im[1], aP);
    aN = f2fma(re[4], re[4], aN); aN = f2fma(im[4], im[4], aN);
    aN = f2fma(re[5], re[5], aN); aN = f2fma(im[5], im[5], aN);
    dP = f2fma(re[2], re[2], dP); dP = f2fma(im[2], im[2], dP);
    dP = f2fma(re[3], re[3], dP); dP = f2fma(im[3], im[3], dP);
    dN = f2fma(re[6], re[6], dN); dN = f2fma(im[6], im[6], dN);
    dN = f2fma(re[7], re[7], dN); dN = f2fma(im[7], im[7], dN);
    rp = f2fma(re[2], re[6], rp); rp = f2fma(im[2], im[6], rp);
    rp = f2fma(re[3], re[7], rp); rp = f2fma(im[3], im[7], rp);
    ip = f2fma(im[2], re[6], ip); ip = f2fma(im[3], re[7], ip);
    in_ = f2fma(re[2], im[6], in_); in_ = f2fma(re[3], im[7], in_);

    float w0 = __ldg(g_w + ch * 3 + 0);
    float w1 = __ldg(g_w + ch * 3 + 1);
    float w2 = __ldg(g_w + ch * 3 + 2);

    float l, h;
    upk(aP, l, h);  float A0 = l + h;
    upk(aN, l, h);  float A1 = l + h;
    upk(dP, l, h);  float D0 = l + h;
    upk(dN, l, h);  float D1 = l + h;
    upk(rp, l, h);  float RP = l + h;
    upk(ip, l, h);  float IP = l + h;
    upk(in_, l, h); float IN = l + h;

    float z = (A0 - A1) + w0 * (D0 - D1) - w1 * (IP - IN) + w2 * RP;
#pragma unroll
    for (int o = 16; o > 0; o >>= 1)
        z += __shfl_xor_sync(FULLMASK, z, o);

    if (lane == 0) {
        out[((b * 30 + r_ + 1) * 30 + (c_ + 1)) * 4 + ch] = (z + 1.0f) * 0.5f;
    }
}

extern "C" void kernel_launch(void* const* d_in, const int* in_sizes, int n_in,
                              void* d_out, int out_size) {
    const float* x  = (const float*)d_in[0];
    const float* qp = (const float*)d_in[1];
    if (n_in >= 2 && in_sizes[0] == 64) {
        const float* t = x; x = qp; qp = t;
    }
    float* out = (float*)d_out;

    prep_kernel<<<(28800 + 255) / 256, 256>>>(x, qp, out);
    sim_kernel<<<3136, 256>>>(out);
}

// round 11
// speedup vs baseline: 3.1020x; 1.9640x over previous
#include <cuda_runtime.h>
#include <cuda_bf16.h>

// ---------------------------------------------------------------------------
// Quanv3x3 quantum layer — CLOSED-FORM factorized simulation.
//
// The circuit's entangling gates split into two disjoint qubit groups:
//   A = {q0,q1,q2,q3}: gates (1,0), (3,2), (2,0)
//   B = {q4,q5,q6,q7,q8}: gates (8,7), (5,4), (7,6), (6,4)
// joined only by the final gate (4,0), which is folded into the observable:
//   z = PB0*(p0-p1) + PB1*[w0*(p0-p1) + w2*Re(t) - w1*Im(t)]
//   w0 = cos(th15), w1 = 2 sin(th15) cos(th14), w2 = 2 sin(th15) sin(th14)
// where p0,p1,t come from the reduced q0 density matrix of Psi_A and
// PB0,PB1 = P(q4=0/1) of Psi_B.
//
// Within each group, gates act on product substates until one coupling
// rotation, so everything reduces to 4-amp pair states S,T,C,D and 2x2
// rotations M2,M5,M6 — ~300 flops per simulation. One THREAD per sim.
// ---------------------------------------------------------------------------

__device__ float g_s[7200];   // sin(pi * avg) per (b,row,col)
__device__ float g_c[7200];   // cos(pi * avg)
__device__ float g_k[4 * 32]; // per-channel gate constants (31 used)

struct c2 { float r, i; };

__device__ __forceinline__ float nrm(c2 a) { return a.r * a.r + a.i * a.i; }
// a * conj(b)
__device__ __forceinline__ c2 cprod(c2 a, c2 b) {
    return { a.r * b.r + a.i * b.i, a.i * b.r - a.r * b.i };
}

// Build the 4-amplitude pair state after CRZ(za)+CRX(xb) with ctrl qubit
// (sin=sc,cos=cc) and tgt qubit (st,ct), both starting as RX-product states
// u = (s, i*c).  Index order: X[ctrl][tgt].
__device__ __forceinline__ void build_pair(
    float sc, float cc, float st, float ct,
    float zc, float zs, float xc, float xs,
    c2& X00, c2& X01, c2& X10, c2& X11)
{
    X00 = { sc * st, 0.0f };
    X01 = { 0.0f, sc * ct };
    // ctrl=1 row: multiply by e^{-i za} / e^{+i za}, then RX mix.
    float y10r =  cc * st * zs, y10i =  cc * st * zc;   // (i*cc*st)*e^{-iza}
    float y11r = -cc * ct * zc, y11i = -cc * ct * zs;   // (-cc*ct)*e^{+iza}
    X10 = { xc * y10r + xs * y11i,  xc * y10i - xs * y11r };
    X11 = { xs * y10i + xc * y11r, -xs * y10r + xc * y11i };
}

// Apply M = RX(xb)*RZ(za) (SU(2): [[al, -conj(be)],[be, conj(al)]]) to the
// (a=tgt0, b=tgt1) amplitude pair.
__device__ __forceinline__ void mapply(c2 al, c2 be, c2 a, c2 b, c2& o0, c2& o1) {
    o0.r = al.r * a.r - al.i * a.i - be.r * b.r - be.i * b.i;
    o0.i = al.r * a.i + al.i * a.r - be.r * b.i + be.i * b.r;
    o1.r = be.r * a.r - be.i * a.i + al.r * b.r + al.i * b.i;
    o1.i = be.r * a.i + be.i * a.r + al.r * b.i - al.i * b.r;
}

__global__ void prep_kernel(const float* __restrict__ x,
                            const float* __restrict__ qp,
                            float* __restrict__ out) {
    int i = blockIdx.x * blockDim.x + threadIdx.x;
    if (i < 28800) out[i] = 0.0f;
    if (i < 7200) {
        const float* p = x + i * 3;
        float a = (p[0] + p[1] + p[2]) * (1.0f / 3.0f);
        float sv, cv;
        sincosf(3.14159265358979323846f * a, &sv, &cv);
        g_s[i] = sv;
        g_c[i] = cv;
    }
    if (i < 4) {
        const float* th = qp + i * 16;
        float* k = g_k + i * 32;
        float hs[16], hc[16];
#pragma unroll
        for (int j = 0; j < 16; j++) sincosf(th[j] * 0.5f, &hs[j], &hc[j]);
        // gate0 (1,0): CRZ th0, CRX th1
        k[0] = hc[0];  k[1] = hs[0];  k[2] = hc[1];  k[3] = hs[1];
        // gate1 (3,2): CRZ th2, CRX th3
        k[4] = hc[2];  k[5] = hs[2];  k[6] = hc[3];  k[7] = hs[3];
        // M2 from (th4 z, th5 x): al = (xc*zc, -xc*zs); be = (-xs*zs, -xs*zc)
        k[8]  =  hc[5] * hc[4];  k[9]  = -hc[5] * hs[4];
        k[10] = -hs[5] * hs[4];  k[11] = -hs[5] * hc[4];
        // gate3 (8,7): CRZ th6, CRX th7
        k[12] = hc[6]; k[13] = hs[6]; k[14] = hc[7]; k[15] = hs[7];
        // gate4 (5,4): CRZ th8, CRX th9
        k[16] = hc[8]; k[17] = hs[8]; k[18] = hc[9]; k[19] = hs[9];
        // M5 from (th10 z, th11 x)
        k[20] =  hc[11] * hc[10]; k[21] = -hc[11] * hs[10];
        k[22] = -hs[11] * hs[10]; k[23] = -hs[11] * hc[10];
        // M6 from (th12 z, th13 x)
        k[24] =  hc[13] * hc[12]; k[25] = -hc[13] * hs[12];
        k[26] = -hs[13] * hs[12]; k[27] = -hs[13] * hc[12];
        // observable weights from FULL angles th14 (z), th15 (x)
        float s15, c15, s14, c14;
        sincosf(th[15], &s15, &c15);
        sincosf(th[14], &s14, &c14);
        k[28] = c15;
        k[29] = 2.0f * s15 * c14;
        k[30] = 2.0f * s15 * s14;
    }
}

__global__ void sim_kernel(float* __restrict__ out) {
    int t = blockIdx.x * blockDim.x + threadIdx.x;
    if (t >= 25088) return;

    int b   = t / 3136;
    int rem = t - b * 3136;
    int ch  = rem / 784;
    int pos = rem - ch * 784;
    int r_  = pos / 28;
    int c_  = pos - r_ * 28;

    // ---- 9 patch-pixel sincos values (s = sin(pi p), c = cos(pi p))
    float ps[9], pc[9];
    int base = b * 900 + r_ * 30 + c_;
#pragma unroll
    for (int dr = 0; dr < 3; dr++)
#pragma unroll
        for (int dc = 0; dc < 3; dc++) {
            int idx = base + dr * 30 + dc;
            ps[dr * 3 + dc] = __ldg(g_s + idx);
            pc[dr * 3 + dc] = __ldg(g_c + idx);
        }

    const float* k = g_k + ch * 32;

    // =================== Group A: qubits {0,1,2,3} =======================
    // S(q1,q0): gate (1,0)
    c2 S00, S01, S10, S11;
    build_pair(ps[1], pc[1], ps[0], pc[0],
               __ldg(k + 0), __ldg(k + 1), __ldg(k + 2), __ldg(k + 3),
               S00, S01, S10, S11);
    // T(q3,q2): gate (3,2)
    c2 T00, T01, T10, T11;
    build_pair(ps[3], pc[3], ps[2], pc[2],
               __ldg(k + 4), __ldg(k + 5), __ldg(k + 6), __ldg(k + 7),
               T00, T01, T10, T11);
    // gate (2,0): M2 on q0 for the q2=1 branch
    c2 a2 = { __ldg(k + 8), __ldg(k + 9) };
    c2 b2 = { __ldg(k + 10), __ldg(k + 11) };
    c2 P00, P01, P10, P11;           // S2 = M2(q0) applied to S
    mapply(a2, b2, S00, S01, P00, P01);
    mapply(a2, b2, S10, S11, P10, P11);

    float T0n = nrm(T00) + nrm(T10);
    float T1n = nrm(T01) + nrm(T11);
    float n0S = nrm(S00) + nrm(S10);
    float n1S = nrm(S01) + nrm(S11);
    c2 tS; { c2 u = cprod(S00, S01), v = cprod(S10, S11); tS = { u.r + v.r, u.i + v.i }; }
    float n0P = nrm(P00) + nrm(P10);
    float n1P = nrm(P01) + nrm(P11);
    c2 tP; { c2 u = cprod(P00, P01), v = cprod(P10, P11); tP = { u.r + v.r, u.i + v.i }; }

    float p0 = T0n * n0S + T1n * n0P;
    float p1 = T0n * n1S + T1n * n1P;
    float tr = T0n * tS.r + T1n * tP.r;
    float ti = T0n * tS.i + T1n * tP.i;

    // =================== Group B: qubits {4..8} ==========================
    // C(q8,q7): gate (8,7)
    c2 C00, C01, C10, C11;
    build_pair(ps[8], pc[8], ps[7], pc[7],
               __ldg(k + 12), __ldg(k + 13), __ldg(k + 14), __ldg(k + 15),
               C00, C01, C10, C11);
    // D(q5,q4): gate (5,4)
    c2 D00, D01, D10, D11;
    build_pair(ps[5], pc[5], ps[4], pc[4],
               __ldg(k + 16), __ldg(k + 17), __ldg(k + 18), __ldg(k + 19),
               D00, D01, D10, D11);
    float Cn0 = nrm(C00) + nrm(C10);
    float Cn1 = nrm(C01) + nrm(C11);

    // gate (7,6): v6 = M5 * u6 (q7=1 branch of q6 state)
    c2 a5 = { __ldg(k + 20), __ldg(k + 21) };
    c2 b5 = { __ldg(k + 22), __ldg(k + 23) };
    c2 u60 = { ps[6], 0.0f }, u61 = { 0.0f, pc[6] };
    c2 v60, v61;
    mapply(a5, b5, u60, u61, v60, v61);
    float wn00 = ps[6] * ps[6], wn01 = pc[6] * pc[6];
    float wn10 = nrm(v60), wn11 = nrm(v61);

    // gate (6,4): D6 = M6(q4) applied to D (q6=1 branch)
    c2 a6 = { __ldg(k + 24), __ldg(k + 25) };
    c2 b6 = { __ldg(k + 26), __ldg(k + 27) };
    c2 E00, E01, E10, E11;
    mapply(a6, b6, D00, D01, E00, E01);
    mapply(a6, b6, D10, D11, E10, E11);

    float DnD0 = nrm(D00) + nrm(D10);
    float DnD1 = nrm(D01) + nrm(D11);
    float Dn60 = nrm(E00) + nrm(E10);
    float Dn61 = nrm(E01) + nrm(E11);

    float PB0 = Cn0 * (wn00 * DnD0 + wn01 * Dn60) +
                Cn1 * (wn10 * DnD0 + wn11 * Dn60);
    float PB1 = Cn0 * (wn00 * DnD1 + wn01 * Dn61) +
                Cn1 * (wn10 * DnD1 + wn11 * Dn61);

    // =================== observable (gate (4,0) folded) ==================
    float w0 = __ldg(k + 28), w1 = __ldg(k + 29), w2 = __ldg(k + 30);
    float dz = p0 - p1;
    float z = PB0 * dz + PB1 * (w0 * dz + w2 * tr - w1 * ti);

    out[((b * 30 + r_ + 1) * 30 + (c_ + 1)) * 4 + ch] = (z + 1.0f) * 0.5f;
}

extern "C" void kernel_launch(void* const* d_in, const int* in_sizes, int n_in,
                              void* d_out, int out_size) {
    const float* x  = (const float*)d_in[0];
    const float* qp = (const float*)d_in[1];
    if (n_in >= 2 && in_sizes[0] == 64) {
        const float* tp = x; x = qp; qp = tp;
    }
    float* out = (float*)d_out;

    prep_kernel<<<(28800 + 255) / 256, 256>>>(x, qp, out);
    sim_kernel<<<392, 64>>>(out);
}

// round 12
// speedup vs baseline: 5.7232x; 1.8450x over previous
#include <cuda_runtime.h>
#include <cuda_bf16.h>

// ---------------------------------------------------------------------------
// Quanv3x3 quantum layer — CLOSED-FORM factorized simulation, SINGLE KERNEL.
//
// Circuit factorizes: group A = {q0..q3} (gates (1,0),(3,2),(2,0)),
// group B = {q4..q8} (gates (8,7),(5,4),(7,6),(6,4)), coupled only by the
// final gate (4,0), folded into the observable:
//   z = PB0*(p0-p1) + PB1*[w0*(p0-p1) + w2*Re(t) - w1*Im(t)]
// with p0,p1,t from the reduced q0 density matrix of Psi_A and PB0/PB1 the
// q4 populations of Psi_B. ~300 flops per sim, one THREAD per sim.
//
// One thread per OUTPUT element (28800): interior threads simulate, border
// threads write the zero padding. Per-channel gate constants built
// cooperatively in shared memory at block start (R11 lesson: the separate
// prep kernel + its launch cost 2x the actual sim time).
// ---------------------------------------------------------------------------

struct c2 { float r, i; };

__device__ __forceinline__ float nrm(c2 a) { return a.r * a.r + a.i * a.i; }
// a * conj(b)
__device__ __forceinline__ c2 cprod(c2 a, c2 b) {
    return { a.r * b.r + a.i * b.i, a.i * b.r - a.r * b.i };
}

// Pair state after CRZ(za)+CRX(xb): ctrl qubit (sc,cc), tgt qubit (st,ct),
// both starting as RX-product states u = (s, i*c). Index: X[ctrl][tgt].
__device__ __forceinline__ void build_pair(
    float sc, float cc, float st, float ct,
    float zc, float zs, float xc, float xs,
    c2& X00, c2& X01, c2& X10, c2& X11)
{
    X00 = { sc * st, 0.0f };
    X01 = { 0.0f, sc * ct };
    float y10r =  cc * st * zs, y10i =  cc * st * zc;   // (i*cc*st)*e^{-iza}
    float y11r = -cc * ct * zc, y11i = -cc * ct * zs;   // (-cc*ct)*e^{+iza}
    X10 = { xc * y10r + xs * y11i,  xc * y10i - xs * y11r };
    X11 = { xs * y10i + xc * y11r, -xs * y10r + xc * y11i };
}

// Apply M = RX(xb)*RZ(za) (SU(2): [[al, -conj(be)],[be, conj(al)]]) to the
// (a=tgt0, b=tgt1) pair.
__device__ __forceinline__ void mapply(c2 al, c2 be, c2 a, c2 b, c2& o0, c2& o1) {
    o0.r = al.r * a.r - al.i * a.i - be.r * b.r - be.i * b.i;
    o0.i = al.r * a.i + al.i * a.r - be.r * b.i + be.i * b.r;
    o1.r = be.r * a.r - be.i * a.i + al.r * b.r + al.i * b.i;
    o1.i = be.r * a.i + be.i * a.r + al.r * b.i - al.i * b.r;
}

#define KW 33   // smem row stride (pad to kill 4-way bank conflicts)

__global__ __launch_bounds__(256) void fused_kernel(
    const float* __restrict__ x,
    const float* __restrict__ qp,
    float* __restrict__ out)
{
    __shared__ float hs[64], hc[64];   // sincos(theta/2) for all 4x16 params
    __shared__ float fw[8], fwc[8];    // full-angle sincos of th14/th15 per ch
    __shared__ float k[4 * KW];        // derived gate constants per channel

    int tid = threadIdx.x;

    // ---- phase 1: raw sincos of parameters --------------------------------
    if (tid < 64) {
        float s, c;
        sincosf(qp[tid] * 0.5f, &s, &c);
        hs[tid] = s; hc[tid] = c;
    } else if (tid < 72) {
        int j = tid - 64;            // j = ch*2 + (0: th14, 1: th15)
        int ch = j >> 1;
        float s, c;
        sincosf(qp[ch * 16 + 14 + (j & 1)], &s, &c);
        fw[j] = s; fwc[j] = c;
    }
    __syncthreads();

    // ---- phase 2: derived constants (products only) -----------------------
    if (tid < 4) {
        const float* s_ = hs + tid * 16;
        const float* c_ = hc + tid * 16;
        float* kk = k + tid * KW;
        kk[0] = c_[0];  kk[1] = s_[0];  kk[2] = c_[1];  kk[3] = s_[1];
        kk[4] = c_[2];  kk[5] = s_[2];  kk[6] = c_[3];  kk[7] = s_[3];
        kk[8]  =  c_[5] * c_[4];  kk[9]  = -c_[5] * s_[4];
        kk[10] = -s_[5] * s_[4];  kk[11] = -s_[5] * c_[4];
        kk[12] = c_[6]; kk[13] = s_[6]; kk[14] = c_[7]; kk[15] = s_[7];
        kk[16] = c_[8]; kk[17] = s_[8]; kk[18] = c_[9]; kk[19] = s_[9];
        kk[20] =  c_[11] * c_[10]; kk[21] = -c_[11] * s_[10];
        kk[22] = -s_[11] * s_[10]; kk[23] = -s_[11] * c_[10];
        kk[24] =  c_[13] * c_[12]; kk[25] = -c_[13] * s_[12];
        kk[26] = -s_[13] * s_[12]; kk[27] = -s_[13] * c_[12];
        float s14 = fw[tid * 2 + 0], c14 = fwc[tid * 2 + 0];
        float s15 = fw[tid * 2 + 1], c15 = fwc[tid * 2 + 1];
        kk[28] = c15;
        kk[29] = 2.0f * s15 * c14;
        kk[30] = 2.0f * s15 * s14;
    }
    __syncthreads();

    // ---- one thread per output element ------------------------------------
    int t = blockIdx.x * blockDim.x + tid;
    if (t >= 28800) return;

    int ch   = t & 3;
    int cell = t >> 2;
    int cc   = cell % 30;
    int rc   = cell / 30;
    int rr   = rc % 30;
    int b    = rc / 30;

    if (rr < 1 || rr > 28 || cc < 1 || cc > 28) {
        out[t] = 0.0f;
        return;
    }
    int r_ = rr - 1, c_ = cc - 1;

    // ---- 9 patch-pixel sincos: s = sin(pi*avg), c = cos(pi*avg) -----------
    float ps[9], pc[9];
    const float* xb = x + (b * 900 + r_ * 30 + c_) * 3;
#pragma unroll
    for (int dr = 0; dr < 3; dr++)
#pragma unroll
        for (int dc = 0; dc < 3; dc++) {
            const float* p = xb + (dr * 30 + dc) * 3;
            float a = (p[0] + p[1] + p[2]) * (1.0f / 3.0f);
            sincospif(a, &ps[dr * 3 + dc], &pc[dr * 3 + dc]);
        }

    const float* kk = k + ch * KW;

    // =================== Group A: qubits {0,1,2,3} =========================
    c2 S00, S01, S10, S11;
    build_pair(ps[1], pc[1], ps[0], pc[0],
               kk[0], kk[1], kk[2], kk[3], S00, S01, S10, S11);
    c2 T00, T01, T10, T11;
    build_pair(ps[3], pc[3], ps[2], pc[2],
               kk[4], kk[5], kk[6], kk[7], T00, T01, T10, T11);
    c2 a2 = { kk[8], kk[9] };
    c2 b2 = { kk[10], kk[11] };
    c2 P00, P01, P10, P11;
    mapply(a2, b2, S00, S01, P00, P01);
    mapply(a2, b2, S10, S11, P10, P11);

    float T0n = nrm(T00) + nrm(T10);
    float T1n = nrm(T01) + nrm(T11);
    float n0S = nrm(S00) + nrm(S10);
    float n1S = nrm(S01) + nrm(S11);
    c2 tS; { c2 u = cprod(S00, S01), v = cprod(S10, S11); tS = { u.r + v.r, u.i + v.i }; }
    float n0P = nrm(P00) + nrm(P10);
    float n1P = nrm(P01) + nrm(P11);
    c2 tP; { c2 u = cprod(P00, P01), v = cprod(P10, P11); tP = { u.r + v.r, u.i + v.i }; }

    float p0 = T0n * n0S + T1n * n0P;
    float p1 = T0n * n1S + T1n * n1P;
    float tr = T0n * tS.r + T1n * tP.r;
    float ti = T0n * tS.i + T1n * tP.i;

    // =================== Group B: qubits {4..8} ============================
    c2 C00, C01, C10, C11;
    build_pair(ps[8], pc[8], ps[7], pc[7],
               kk[12], kk[13], kk[14], kk[15], C00, C01, C10, C11);
    c2 D00, D01, D10, D11;
    build_pair(ps[5], pc[5], ps[4], pc[4],
               kk[16], kk[17], kk[18], kk[19], D00, D01, D10, D11);
    float Cn0 = nrm(C00) + nrm(C10);
    float Cn1 = nrm(C01) + nrm(C11);

    c2 a5 = { kk[20], kk[21] };
    c2 b5 = { kk[22], kk[23] };
    c2 u60 = { ps[6], 0.0f }, u61 = { 0.0f, pc[6] };
    c2 v60, v61;
    mapply(a5, b5, u60, u61, v60, v61);
    float wn00 = ps[6] * ps[6], wn01 = pc[6] * pc[6];
    float wn10 = nrm(v60), wn11 = nrm(v61);

    c2 a6 = { kk[24], kk[25] };
    c2 b6 = { kk[26], kk[27] };
    c2 E00, E01, E10, E11;
    mapply(a6, b6, D00, D01, E00, E01);
    mapply(a6, b6, D10, D11, E10, E11);

    float DnD0 = nrm(D00) + nrm(D10);
    float DnD1 = nrm(D01) + nrm(D11);
    float Dn60 = nrm(E00) + nrm(E10);
    float Dn61 = nrm(E01) + nrm(E11);

    float PB0 = Cn0 * (wn00 * DnD0 + wn01 * Dn60) +
                Cn1 * (wn10 * DnD0 + wn11 * Dn60);
    float PB1 = Cn0 * (wn00 * DnD1 + wn01 * Dn61) +
                Cn1 * (wn10 * DnD1 + wn11 * Dn61);

    // =================== observable (gate (4,0) folded) ====================
    float w0 = kk[28], w1 = kk[29], w2 = kk[30];
    float dz = p0 - p1;
    float z = PB0 * dz + PB1 * (w0 * dz + w2 * tr - w1 * ti);

    out[t] = (z + 1.0f) * 0.5f;
}

extern "C" void kernel_launch(void* const* d_in, const int* in_sizes, int n_in,
                              void* d_out, int out_size) {
    const float* x  = (const float*)d_in[0];
    const float* qp = (const float*)d_in[1];
    if (n_in >= 2 && in_sizes[0] == 64) {
        const float* tp = x; x = qp; qp = tp;
    }
    float* out = (float*)d_out;

    fused_kernel<<<(28800 + 255) / 256, 256>>>(x, qp, out);
}

// round 13
// speedup vs baseline: 7.1806x; 1.2546x over previous
#include <cuda_runtime.h>
#include <cuda_bf16.h>

// ---------------------------------------------------------------------------
// Quanv3x3 quantum layer — CLOSED-FORM factorized sim, single kernel,
// fast-math sincos (rel_err budget 1e-3; full-precision was 2e-7, fast
// MUFU approx lands ~1e-5).
//
// Factorization: group A = {q0..q3} (gates (1,0),(3,2),(2,0)),
// group B = {q4..q8} (gates (8,7),(5,4),(7,6),(6,4)); final gate (4,0)
// folded into the observable:
//   z = PB0*(p0-p1) + PB1*[w0*(p0-p1) + w2*Re(t) - w1*Im(t)]
// ~300 flops/sim, one THREAD per output element (28800).
//
// 64-thread blocks -> 450 blocks: all 148 SMs busy (256-thread grid left
// 35 SMs idle). Constants built in smem per block.
// ---------------------------------------------------------------------------

struct c2 { float r, i; };

__device__ __forceinline__ float nrm(c2 a) { return a.r * a.r + a.i * a.i; }
// a * conj(b)
__device__ __forceinline__ c2 cprod(c2 a, c2 b) {
    return { a.r * b.r + a.i * b.i, a.i * b.r - a.r * b.i };
}

// Pair state after CRZ(za)+CRX(xb): ctrl qubit (sc,cc), tgt qubit (st,ct),
// both starting as RX-product states u = (s, i*c). Index: X[ctrl][tgt].
__device__ __forceinline__ void build_pair(
    float sc, float cc, float st, float ct,
    float zc, float zs, float xc, float xs,
    c2& X00, c2& X01, c2& X10, c2& X11)
{
    X00 = { sc * st, 0.0f };
    X01 = { 0.0f, sc * ct };
    float y10r =  cc * st * zs, y10i =  cc * st * zc;   // (i*cc*st)*e^{-iza}
    float y11r = -cc * ct * zc, y11i = -cc * ct * zs;   // (-cc*ct)*e^{+iza}
    X10 = { xc * y10r + xs * y11i,  xc * y10i - xs * y11r };
    X11 = { xs * y10i + xc * y11r, -xs * y10r + xc * y11i };
}

// Apply M = RX(xb)*RZ(za) (SU(2): [[al, -conj(be)],[be, conj(al)]]).
__device__ __forceinline__ void mapply(c2 al, c2 be, c2 a, c2 b, c2& o0, c2& o1) {
    o0.r = al.r * a.r - al.i * a.i - be.r * b.r - be.i * b.i;
    o0.i = al.r * a.i + al.i * a.r - be.r * b.i + be.i * b.r;
    o1.r = be.r * a.r - be.i * a.i + al.r * b.r + al.i * b.i;
    o1.i = be.r * a.i + be.i * a.r + al.r * b.i - al.i * b.r;
}

#define KW 33   // smem row stride (pad to kill bank conflicts)
#define NT 64   // threads per block

__global__ __launch_bounds__(NT) void fused_kernel(
    const float* __restrict__ x,
    const float* __restrict__ qp,
    float* __restrict__ out)
{
    __shared__ float hs[64], hc[64];   // sincos(theta/2) for all 4x16 params
    __shared__ float fw[8], fwc[8];    // full-angle sincos of th14/th15 per ch
    __shared__ float k[4 * KW];        // derived gate constants per channel

    int tid = threadIdx.x;

    // ---- phase 1: raw sincos of parameters (fast MUFU path) ---------------
    {
        float s, c;
        __sincosf(__ldg(qp + tid) * 0.5f, &s, &c);
        hs[tid] = s; hc[tid] = c;
        if (tid < 8) {
            int ch = tid >> 1;
            float s2, c2v;
            __sincosf(__ldg(qp + ch * 16 + 14 + (tid & 1)), &s2, &c2v);
            fw[tid] = s2; fwc[tid] = c2v;
        }
    }
    __syncthreads();

    // ---- phase 2: derived constants (products only) -----------------------
    if (tid < 4) {
        const float* s_ = hs + tid * 16;
        const float* c_ = hc + tid * 16;
        float* kk = k + tid * KW;
        kk[0] = c_[0];  kk[1] = s_[0];  kk[2] = c_[1];  kk[3] = s_[1];
        kk[4] = c_[2];  kk[5] = s_[2];  kk[6] = c_[3];  kk[7] = s_[3];
        kk[8]  =  c_[5] * c_[4];  kk[9]  = -c_[5] * s_[4];
        kk[10] = -s_[5] * s_[4];  kk[11] = -s_[5] * c_[4];
        kk[12] = c_[6]; kk[13] = s_[6]; kk[14] = c_[7]; kk[15] = s_[7];
        kk[16] = c_[8]; kk[17] = s_[8]; kk[18] = c_[9]; kk[19] = s_[9];
        kk[20] =  c_[11] * c_[10]; kk[21] = -c_[11] * s_[10];
        kk[22] = -s_[11] * s_[10]; kk[23] = -s_[11] * c_[10];
        kk[24] =  c_[13] * c_[12]; kk[25] = -c_[13] * s_[12];
        kk[26] = -s_[13] * s_[12]; kk[27] = -s_[13] * c_[12];
        float s14 = fw[tid * 2 + 0], c14 = fwc[tid * 2 + 0];
        float s15 = fw[tid * 2 + 1], c15 = fwc[tid * 2 + 1];
        kk[28] = c15;
        kk[29] = 2.0f * s15 * c14;
        kk[30] = 2.0f * s15 * s14;
    }
    __syncthreads();

    // ---- one thread per output element ------------------------------------
    int t = blockIdx.x * NT + tid;
    if (t >= 28800) return;

    int ch   = t & 3;
    int cell = t >> 2;
    int cc   = cell % 30;
    int rc   = cell / 30;
    int rr   = rc % 30;
    int b    = rc / 30;

    if (rr < 1 || rr > 28 || cc < 1 || cc > 28) {
        out[t] = 0.0f;
        return;
    }
    int r_ = rr - 1, c_ = cc - 1;

    // ---- 9 patch-pixel sincos: s = sin(pi*avg), c = cos(pi*avg) -----------
    const float PI = 3.14159265358979323846f;
    float ps[9], pc[9];
    const float* xb = x + (b * 900 + r_ * 30 + c_) * 3;
#pragma unroll
    for (int dr = 0; dr < 3; dr++)
#pragma unroll
        for (int dc = 0; dc < 3; dc++) {
            const float* p = xb + (dr * 30 + dc) * 3;
            float a = (__ldg(p + 0) + __ldg(p + 1) + __ldg(p + 2)) * (1.0f / 3.0f);
            __sincosf(PI * a, &ps[dr * 3 + dc], &pc[dr * 3 + dc]);
        }

    const float* kk = k + ch * KW;

    // =================== Group A: qubits {0,1,2,3} =========================
    c2 S00, S01, S10, S11;
    build_pair(ps[1], pc[1], ps[0], pc[0],
               kk[0], kk[1], kk[2], kk[3], S00, S01, S10, S11);
    c2 T00, T01, T10, T11;
    build_pair(ps[3], pc[3], ps[2], pc[2],
               kk[4], kk[5], kk[6], kk[7], T00, T01, T10, T11);
    c2 a2 = { kk[8], kk[9] };
    c2 b2 = { kk[10], kk[11] };
    c2 P00, P01, P10, P11;
    mapply(a2, b2, S00, S01, P00, P01);
    mapply(a2, b2, S10, S11, P10, P11);

    float T0n = nrm(T00) + nrm(T10);
    float T1n = nrm(T01) + nrm(T11);
    float n0S = nrm(S00) + nrm(S10);
    float n1S = nrm(S01) + nrm(S11);
    c2 tS; { c2 u = cprod(S00, S01), v = cprod(S10, S11); tS = { u.r + v.r, u.i + v.i }; }
    float n0P = nrm(P00) + nrm(P10);
    float n1P = nrm(P01) + nrm(P11);
    c2 tP; { c2 u = cprod(P00, P01), v = cprod(P10, P11); tP = { u.r + v.r, u.i + v.i }; }

    float p0 = T0n * n0S + T1n * n0P;
    float p1 = T0n * n1S + T1n * n1P;
    float tr = T0n * tS.r + T1n * tP.r;
    float ti = T0n * tS.i + T1n * tP.i;

    // =================== Group B: qubits {4..8} ============================
    c2 C00, C01, C10, C11;
    build_pair(ps[8], pc[8], ps[7], pc[7],
               kk[12], kk[13], kk[14], kk[15], C00, C01, C10, C11);
    c2 D00, D01, D10, D11;
    build_pair(ps[5], pc[5], ps[4], pc[4],
               kk[16], kk[17], kk[18], kk[19], D00, D01, D10, D11);
    float Cn0 = nrm(C00) + nrm(C10);
    float Cn1 = nrm(C01) + nrm(C11);

    c2 a5 = { kk[20], kk[21] };
    c2 b5 = { kk[22], kk[23] };
    c2 u60 = { ps[6], 0.0f }, u61 = { 0.0f, pc[6] };
    c2 v60, v61;
    mapply(a5, b5, u60, u61, v60, v61);
    float wn00 = ps[6] * ps[6], wn01 = pc[6] * pc[6];
    float wn10 = nrm(v60), wn11 = nrm(v61);

    c2 a6 = { kk[24], kk[25] };
    c2 b6 = { kk[26], kk[27] };
    c2 E00, E01, E10, E11;
    mapply(a6, b6, D00, D01, E00, E01);
    mapply(a6, b6, D10, D11, E10, E11);

    float DnD0 = nrm(D00) + nrm(D10);
    float DnD1 = nrm(D01) + nrm(D11);
    float Dn60 = nrm(E00) + nrm(E10);
    float Dn61 = nrm(E01) + nrm(E11);

    float PB0 = Cn0 * (wn00 * DnD0 + wn01 * Dn60) +
                Cn1 * (wn10 * DnD0 + wn11 * Dn60);
    float PB1 = Cn0 * (wn00 * DnD1 + wn01 * Dn61) +
                Cn1 * (wn10 * DnD1 + wn11 * Dn61);

    // =================== observable (gate (4,0) folded) ====================
    float w0 = kk[28], w1 = kk[29], w2 = kk[30];
    float dz = p0 - p1;
    float z = PB0 * dz + PB1 * (w0 * dz + w2 * tr - w1 * ti);

    out[t] = (z + 1.0f) * 0.5f;
}

extern "C" void kernel_launch(void* const* d_in, const int* in_sizes, int n_in,
                              void* d_out, int out_size) {
    const float* x  = (const float*)d_in[0];
    const float* qp = (const float*)d_in[1];
    if (n_in >= 2 && in_sizes[0] == 64) {
        const float* tp = x; x = qp; qp = tp;
    }
    float* out = (float*)d_out;

    fused_kernel<<<(28800 + NT - 1) / NT, NT>>>(x, qp, out);
}

// round 14
// speedup vs baseline: 7.2140x; 1.0047x over previous
#include <cuda_runtime.h>
#include <cuda_bf16.h>

// ---------------------------------------------------------------------------
// Quanv3x3 quantum layer — closed-form factorized sim, single kernel,
// WARP-SPLIT: group A (q0..q3) and group B (q4..q8) of each simulation are
// computed by different warps in parallel (warp-uniform roles; a lane-level
// even/odd split would serialize under divergence). Exchange via smem.
//
//   z = PB0*(p0-p1) + PB1*[w0*(p0-p1) + w2*Re(t) - w1*Im(t)]
//
// Block = 128 threads: warps 0,2 -> A for 64 sims; warps 1,3 -> B.
// Then threads 0..63 combine + write. 450 blocks x 128 = 57600 threads.
// Fast __sincosf everywhere (rel_err 4.4e-7 vs 1e-3 budget).
// ---------------------------------------------------------------------------

struct c2 { float r, i; };

__device__ __forceinline__ float nrm(c2 a) { return a.r * a.r + a.i * a.i; }
// a * conj(b)
__device__ __forceinline__ c2 cprod(c2 a, c2 b) {
    return { a.r * b.r + a.i * b.i, a.i * b.r - a.r * b.i };
}

// Pair state after CRZ(za)+CRX(xb): ctrl qubit (sc,cc), tgt qubit (st,ct),
// both starting as RX-product states u = (s, i*c). Index: X[ctrl][tgt].
__device__ __forceinline__ void build_pair(
    float sc, float cc, float st, float ct,
    float zc, float zs, float xc, float xs,
    c2& X00, c2& X01, c2& X10, c2& X11)
{
    X00 = { sc * st, 0.0f };
    X01 = { 0.0f, sc * ct };
    float y10r =  cc * st * zs, y10i =  cc * st * zc;   // (i*cc*st)*e^{-iza}
    float y11r = -cc * ct * zc, y11i = -cc * ct * zs;   // (-cc*ct)*e^{+iza}
    X10 = { xc * y10r + xs * y11i,  xc * y10i - xs * y11r };
    X11 = { xs * y10i + xc * y11r, -xs * y10r + xc * y11i };
}

// Apply M = RX(xb)*RZ(za) (SU(2): [[al, -conj(be)],[be, conj(al)]]).
__device__ __forceinline__ void mapply(c2 al, c2 be, c2 a, c2 b, c2& o0, c2& o1) {
    o0.r = al.r * a.r - al.i * a.i - be.r * b.r - be.i * b.i;
    o0.i = al.r * a.i + al.i * a.r - be.r * b.i + be.i * b.r;
    o1.r = be.r * a.r - be.i * a.i + al.r * b.r + al.i * b.i;
    o1.i = be.r * a.i + be.i * a.r + al.r * b.i - al.i * b.r;
}

#define KW 33   // smem row stride for constants
#define PIf 3.14159265358979323846f

__global__ __launch_bounds__(128) void fused_kernel(
    const float* __restrict__ x,
    const float* __restrict__ qp,
    float* __restrict__ out)
{
    __shared__ float hs[64], hc[64];   // sincos(theta/2) of all 64 params
    __shared__ float fw[8], fwc[8];    // full-angle sincos of th14/th15
    __shared__ float k[4 * KW];        // derived gate constants per channel
    __shared__ float sA0[64], sA1[64], sAr[64], sAi[64];  // A results
    __shared__ float sB0[64], sB1[64];                    // B results

    int tid = threadIdx.x;

    // ---- phase 1: raw sincos of parameters --------------------------------
    if (tid < 64) {
        float s, c;
        __sincosf(__ldg(qp + tid) * 0.5f, &s, &c);
        hs[tid] = s; hc[tid] = c;
    } else if (tid < 72) {
        int j = tid - 64;
        int ch = j >> 1;
        float s, c;
        __sincosf(__ldg(qp + ch * 16 + 14 + (j & 1)), &s, &c);
        fw[j] = s; fwc[j] = c;
    }
    __syncthreads();

    // ---- phase 2: derived constants ---------------------------------------
    if (tid < 4) {
        const float* s_ = hs + tid * 16;
        const float* c_ = hc + tid * 16;
        float* kk = k + tid * KW;
        kk[0] = c_[0];  kk[1] = s_[0];  kk[2] = c_[1];  kk[3] = s_[1];
        kk[4] = c_[2];  kk[5] = s_[2];  kk[6] = c_[3];  kk[7] = s_[3];
        kk[8]  =  c_[5] * c_[4];  kk[9]  = -c_[5] * s_[4];
        kk[10] = -s_[5] * s_[4];  kk[11] = -s_[5] * c_[4];
        kk[12] = c_[6]; kk[13] = s_[6]; kk[14] = c_[7]; kk[15] = s_[7];
        kk[16] = c_[8]; kk[17] = s_[8]; kk[18] = c_[9]; kk[19] = s_[9];
        kk[20] =  c_[11] * c_[10]; kk[21] = -c_[11] * s_[10];
        kk[22] = -s_[11] * s_[10]; kk[23] = -s_[11] * c_[10];
        kk[24] =  c_[13] * c_[12]; kk[25] = -c_[13] * s_[12];
        kk[26] = -s_[13] * s_[12]; kk[27] = -s_[13] * c_[12];
        float s14 = fw[tid * 2 + 0], c14 = fwc[tid * 2 + 0];
        float s15 = fw[tid * 2 + 1], c15 = fwc[tid * 2 + 1];
        kk[28] = c15;
        kk[29] = 2.0f * s15 * c14;
        kk[30] = 2.0f * s15 * s14;
    }
    __syncthreads();

    // ---- warp-split sim compute -------------------------------------------
    int warp = tid >> 5, lane = tid & 31;
    int ls   = (warp >> 1) * 32 + lane;     // local sim 0..63
    int role = warp & 1;                     // 0 = group A, 1 = group B
    int sim  = blockIdx.x * 64 + ls;         // 450*64 = 28800 exactly

    int ch   = sim & 3;
    int cell = sim >> 2;
    int cc   = cell % 30;
    int rc   = cell / 30;
    int rr   = rc % 30;
    int b    = rc / 30;

    // clamp (branch-free); border masked at write
    int r_ = min(max(rr - 1, 0), 27);
    int c_ = min(max(cc - 1, 0), 27);

    const float* kk = k + ch * KW;
    const float* xb = x + (b * 900 + r_ * 30 + c_) * 3;

    if (role == 0) {
        // ---- group A: pixels/qubits 0..3 ----------------------------------
        float ps[4], pc_[4];
#pragma unroll
        for (int j = 0; j < 4; j++) {
            int dr = j / 3, dc = j - dr * 3;
            const float* p = xb + (dr * 30 + dc) * 3;
            float a = (__ldg(p + 0) + __ldg(p + 1) + __ldg(p + 2)) * (1.0f / 3.0f);
            __sincosf(PIf * a, &ps[j], &pc_[j]);
        }
        c2 S00, S01, S10, S11;
        build_pair(ps[1], pc_[1], ps[0], pc_[0],
                   kk[0], kk[1], kk[2], kk[3], S00, S01, S10, S11);
        c2 T00, T01, T10, T11;
        build_pair(ps[3], pc_[3], ps[2], pc_[2],
                   kk[4], kk[5], kk[6], kk[7], T00, T01, T10, T11);
        c2 a2 = { kk[8], kk[9] };
        c2 b2 = { kk[10], kk[11] };
        c2 P00, P01, P10, P11;
        mapply(a2, b2, S00, S01, P00, P01);
        mapply(a2, b2, S10, S11, P10, P11);

        float T0n = nrm(T00) + nrm(T10);
        float T1n = nrm(T01) + nrm(T11);
        float n0S = nrm(S00) + nrm(S10);
        float n1S = nrm(S01) + nrm(S11);
        c2 tS; { c2 u = cprod(S00, S01), v = cprod(S10, S11); tS = { u.r + v.r, u.i + v.i }; }
        float n0P = nrm(P00) + nrm(P10);
        float n1P = nrm(P01) + nrm(P11);
        c2 tP; { c2 u = cprod(P00, P01), v = cprod(P10, P11); tP = { u.r + v.r, u.i + v.i }; }

        sA0[ls] = T0n * n0S + T1n * n0P;
        sA1[ls] = T0n * n1S + T1n * n1P;
        sAr[ls] = T0n * tS.r + T1n * tP.r;
        sAi[ls] = T0n * tS.i + T1n * tP.i;
    } else {
        // ---- group B: pixels/qubits 4..8 ----------------------------------
        float ps[5], pc_[5];
#pragma unroll
        for (int j = 0; j < 5; j++) {
            int q = j + 4;
            int dr = q / 3, dc = q - dr * 3;
            const float* p = xb + (dr * 30 + dc) * 3;
            float a = (__ldg(p + 0) + __ldg(p + 1) + __ldg(p + 2)) * (1.0f / 3.0f);
            __sincosf(PIf * a, &ps[j], &pc_[j]);
        }
        // indices: ps[0]=q4, ps[1]=q5, ps[2]=q6, ps[3]=q7, ps[4]=q8
        c2 C00, C01, C10, C11;
        build_pair(ps[4], pc_[4], ps[3], pc_[3],
                   kk[12], kk[13], kk[14], kk[15], C00, C01, C10, C11);
        c2 D00, D01, D10, D11;
        build_pair(ps[1], pc_[1], ps[0], pc_[0],
                   kk[16], kk[17], kk[18], kk[19], D00, D01, D10, D11);
        float Cn0 = nrm(C00) + nrm(C10);
        float Cn1 = nrm(C01) + nrm(C11);

        c2 a5 = { kk[20], kk[21] };
        c2 b5 = { kk[22], kk[23] };
        c2 u60 = { ps[2], 0.0f }, u61 = { 0.0f, pc_[2] };
        c2 v60, v61;
        mapply(a5, b5, u60, u61, v60, v61);
        float wn00 = ps[2] * ps[2], wn01 = pc_[2] * pc_[2];
        float wn10 = nrm(v60), wn11 = nrm(v61);

        c2 a6 = { kk[24], kk[25] };
        c2 b6 = { kk[26], kk[27] };
        c2 E00, E01, E10, E11;
        mapply(a6, b6, D00, D01, E00, E01);
        mapply(a6, b6, D10, D11, E10, E11);

        float DnD0 = nrm(D00) + nrm(D10);
        float DnD1 = nrm(D01) + nrm(D11);
        float Dn60 = nrm(E00) + nrm(E10);
        float Dn61 = nrm(E01) + nrm(E11);

        sB0[ls] = Cn0 * (wn00 * DnD0 + wn01 * Dn60) +
                  Cn1 * (wn10 * DnD0 + wn11 * Dn60);
        sB1[ls] = Cn0 * (wn00 * DnD1 + wn01 * Dn61) +
                  Cn1 * (wn10 * DnD1 + wn11 * Dn61);
    }
    __syncthreads();

    // ---- combine + write (threads 0..63) ----------------------------------
    if (tid < 64) {
        int sim2  = blockIdx.x * 64 + tid;
        int ch2   = sim2 & 3;
        int cell2 = sim2 >> 2;
        int cc2   = cell2 % 30;
        int rc2   = cell2 / 30;
        int rr2   = rc2 % 30;
        const float* kk2 = k + ch2 * KW;

        float dz = sA0[tid] - sA1[tid];
        float z  = sB0[tid] * dz +
                   sB1[tid] * (kk2[28] * dz + kk2[30] * sAr[tid] - kk2[29] * sAi[tid]);
        bool interior = (rr2 >= 1 && rr2 <= 28 && cc2 >= 1 && cc2 <= 28);
        out[sim2] = interior ? (z + 1.0f) * 0.5f : 0.0f;
    }
}

extern "C" void kernel_launch(void* const* d_in, const int* in_sizes, int n_in,
                              void* d_out, int out_size) {
    const float* x  = (const float*)d_in[0];
    const float* qp = (const float*)d_in[1];
    if (n_in >= 2 && in_sizes[0] == 64) {
        const float* tp = x; x = qp; qp = tp;
    }
    float* out = (float*)d_out;

    fused_kernel<<<450, 128>>>(x, qp, out);
}

// round 15
// speedup vs baseline: 7.4928x; 1.0386x over previous
#include <cuda_runtime.h>
#include <cuda_bf16.h>

// ---------------------------------------------------------------------------
// Quanv3x3 quantum layer — closed-form factorized sim, single kernel,
// warp-split A/B, LATENCY-OVERLAPPED prologue:
//   - pixel loads issued FIRST (independent, MLP~12-15) so their DRAM
//     latency overlaps the constant-building prologue
//   - constants built in ONE phase by threads 0..3 (one per channel),
//     eliminating a __syncthreads and the hs/hc smem round-trip
//
//   z = PB0*(p0-p1) + PB1*[w0*(p0-p1) + w2*Re(t) - w1*Im(t)]
//
// Block = 128 threads: warps 0,2 -> group A (q0..q3) for 64 sims;
// warps 1,3 -> group B (q4..q8). Exchange 6 floats/sim via smem; threads
// 0..63 combine + write. 450 blocks x 64 sims = 28800 outputs exactly.
// ---------------------------------------------------------------------------

struct c2 { float r, i; };

__device__ __forceinline__ float nrm(c2 a) { return a.r * a.r + a.i * a.i; }
// a * conj(b)
__device__ __forceinline__ c2 cprod(c2 a, c2 b) {
    return { a.r * b.r + a.i * b.i, a.i * b.r - a.r * b.i };
}

// Pair state after CRZ(za)+CRX(xb): ctrl qubit (sc,cc), tgt qubit (st,ct),
// both starting as RX-product states u = (s, i*c). Index: X[ctrl][tgt].
__device__ __forceinline__ void build_pair(
    float sc, float cc, float st, float ct,
    float zc, float zs, float xc, float xs,
    c2& X00, c2& X01, c2& X10, c2& X11)
{
    X00 = { sc * st, 0.0f };
    X01 = { 0.0f, sc * ct };
    float y10r =  cc * st * zs, y10i =  cc * st * zc;   // (i*cc*st)*e^{-iza}
    float y11r = -cc * ct * zc, y11i = -cc * ct * zs;   // (-cc*ct)*e^{+iza}
    X10 = { xc * y10r + xs * y11i,  xc * y10i - xs * y11r };
    X11 = { xs * y10i + xc * y11r, -xs * y10r + xc * y11i };
}

// Apply M = RX(xb)*RZ(za) (SU(2): [[al, -conj(be)],[be, conj(al)]]).
__device__ __forceinline__ void mapply(c2 al, c2 be, c2 a, c2 b, c2& o0, c2& o1) {
    o0.r = al.r * a.r - al.i * a.i - be.r * b.r - be.i * b.i;
    o0.i = al.r * a.i + al.i * a.r - be.r * b.i + be.i * b.r;
    o1.r = be.r * a.r - be.i * a.i + al.r * b.r + al.i * b.i;
    o1.i = be.r * a.i + be.i * a.r + al.r * b.i - al.i * b.r;
}

#define KW 33   // smem row stride for constants
#define PIf 3.14159265358979323846f

__global__ __launch_bounds__(128) void fused_kernel(
    const float* __restrict__ x,
    const float* __restrict__ qp,
    float* __restrict__ out)
{
    __shared__ float k[4 * KW];                           // gate constants
    __shared__ float sA0[64], sA1[64], sAr[64], sAi[64];  // A results
    __shared__ float sB0[64], sB1[64];                    // B results

    int tid = threadIdx.x;
    int warp = tid >> 5, lane = tid & 31;
    int ls   = (warp >> 1) * 32 + lane;     // local sim 0..63
    int role = warp & 1;                     // 0 = group A, 1 = group B
    int sim  = blockIdx.x * 64 + ls;

    int ch   = sim & 3;
    int cell = sim >> 2;
    int cc   = cell % 30;
    int rc   = cell / 30;
    int rr   = rc % 30;
    int b    = rc / 30;

    int r_ = min(max(rr - 1, 0), 27);   // clamp; border masked at write
    int c_ = min(max(cc - 1, 0), 27);
    const float* xb = x + (b * 900 + r_ * 30 + c_) * 3;

    // ---- pixel loads FIRST: independent, overlap the prologue -------------
    float px[15];
    if (role == 0) {
#pragma unroll
        for (int j = 0; j < 4; j++) {
            int dr = j / 3, dc = j - dr * 3;
            const float* p = xb + (dr * 30 + dc) * 3;
            px[3 * j + 0] = __ldg(p + 0);
            px[3 * j + 1] = __ldg(p + 1);
            px[3 * j + 2] = __ldg(p + 2);
        }
    } else {
#pragma unroll
        for (int j = 0; j < 5; j++) {
            int q = j + 4;
            int dr = q / 3, dc = q - dr * 3;
            const float* p = xb + (dr * 30 + dc) * 3;
            px[3 * j + 0] = __ldg(p + 0);
            px[3 * j + 1] = __ldg(p + 1);
            px[3 * j + 2] = __ldg(p + 2);
        }
    }

    // ---- single-phase constant build: thread t (<4) does channel t --------
    if (tid < 4) {
        const float* th = qp + tid * 16;
        float s_[16], c_[16];
#pragma unroll
        for (int j = 0; j < 14; j++)
            __sincosf(__ldg(th + j) * 0.5f, &s_[j], &c_[j]);
        float* kk = k + tid * KW;
        kk[0] = c_[0];  kk[1] = s_[0];  kk[2] = c_[1];  kk[3] = s_[1];
        kk[4] = c_[2];  kk[5] = s_[2];  kk[6] = c_[3];  kk[7] = s_[3];
        kk[8]  =  c_[5] * c_[4];  kk[9]  = -c_[5] * s_[4];
        kk[10] = -s_[5] * s_[4];  kk[11] = -s_[5] * c_[4];
        kk[12] = c_[6]; kk[13] = s_[6]; kk[14] = c_[7]; kk[15] = s_[7];
        kk[16] = c_[8]; kk[17] = s_[8]; kk[18] = c_[9]; kk[19] = s_[9];
        kk[20] =  c_[11] * c_[10]; kk[21] = -c_[11] * s_[10];
        kk[22] = -s_[11] * s_[10]; kk[23] = -s_[11] * c_[10];
        kk[24] =  c_[13] * c_[12]; kk[25] = -c_[13] * s_[12];
        kk[26] = -s_[13] * s_[12]; kk[27] = -s_[13] * c_[12];
        float s14, c14, s15, c15;
        __sincosf(__ldg(th + 14), &s14, &c14);
        __sincosf(__ldg(th + 15), &s15, &c15);
        kk[28] = c15;
        kk[29] = 2.0f * s15 * c14;
        kk[30] = 2.0f * s15 * s14;
    }
    __syncthreads();

    const float* kk = k + ch * KW;

    if (role == 0) {
        // ---- group A: pixels/qubits 0..3 ----------------------------------
        float ps[4], pc_[4];
#pragma unroll
        for (int j = 0; j < 4; j++) {
            float a = (px[3 * j] + px[3 * j + 1] + px[3 * j + 2]) * (1.0f / 3.0f);
            __sincosf(PIf * a, &ps[j], &pc_[j]);
        }
        c2 S00, S01, S10, S11;
        build_pair(ps[1], pc_[1], ps[0], pc_[0],
                   kk[0], kk[1], kk[2], kk[3], S00, S01, S10, S11);
        c2 T00, T01, T10, T11;
        build_pair(ps[3], pc_[3], ps[2], pc_[2],
                   kk[4], kk[5], kk[6], kk[7], T00, T01, T10, T11);
        c2 a2 = { kk[8], kk[9] };
        c2 b2 = { kk[10], kk[11] };
        c2 P00, P01, P10, P11;
        mapply(a2, b2, S00, S01, P00, P01);
        mapply(a2, b2, S10, S11, P10, P11);

        float T0n = nrm(T00) + nrm(T10);
        float T1n = nrm(T01) + nrm(T11);
        float n0S = nrm(S00) + nrm(S10);
        float n1S = nrm(S01) + nrm(S11);
        c2 tS; { c2 u = cprod(S00, S01), v = cprod(S10, S11); tS = { u.r + v.r, u.i + v.i }; }
        float n0P = nrm(P00) + nrm(P10);
        float n1P = nrm(P01) + nrm(P11);
        c2 tP; { c2 u = cprod(P00, P01), v = cprod(P10, P11); tP = { u.r + v.r, u.i + v.i }; }

        sA0[ls] = T0n * n0S + T1n * n0P;
        sA1[ls] = T0n * n1S + T1n * n1P;
        sAr[ls] = T0n * tS.r + T1n * tP.r;
        sAi[ls] = T0n * tS.i + T1n * tP.i;
    } else {
        // ---- group B: pixels/qubits 4..8 ----------------------------------
        float ps[5], pc_[5];
#pragma unroll
        for (int j = 0; j < 5; j++) {
            float a = (px[3 * j] + px[3 * j + 1] + px[3 * j + 2]) * (1.0f / 3.0f);
            __sincosf(PIf * a, &ps[j], &pc_[j]);
        }
        // ps[0]=q4, ps[1]=q5, ps[2]=q6, ps[3]=q7, ps[4]=q8
        c2 C00, C01, C10, C11;
        build_pair(ps[4], pc_[4], ps[3], pc_[3],
                   kk[12], kk[13], kk[14], kk[15], C00, C01, C10, C11);
        c2 D00, D01, D10, D11;
        build_pair(ps[1], pc_[1], ps[0], pc_[0],
                   kk[16], kk[17], kk[18], kk[19], D00, D01, D10, D11);
        float Cn0 = nrm(C00) + nrm(C10);
        float Cn1 = nrm(C01) + nrm(C11);

        c2 a5 = { kk[20], kk[21] };
        c2 b5 = { kk[22], kk[23] };
        c2 u60 = { ps[2], 0.0f }, u61 = { 0.0f, pc_[2] };
        c2 v60, v61;
        mapply(a5, b5, u60, u61, v60, v61);
        float wn00 = ps[2] * ps[2], wn01 = pc_[2] * pc_[2];
        float wn10 = nrm(v60), wn11 = nrm(v61);

        c2 a6 = { kk[24], kk[25] };
        c2 b6 = { kk[26], kk[27] };
        c2 E00, E01, E10, E11;
        mapply(a6, b6, D00, D01, E00, E01);
        mapply(a6, b6, D10, D11, E10, E11);

        float DnD0 = nrm(D00) + nrm(D10);
        float DnD1 = nrm(D01) + nrm(D11);
        float Dn60 = nrm(E00) + nrm(E10);
        float Dn61 = nrm(E01) + nrm(E11);

        sB0[ls] = Cn0 * (wn00 * DnD0 + wn01 * Dn60) +
                  Cn1 * (wn10 * DnD0 + wn11 * Dn60);
        sB1[ls] = Cn0 * (wn00 * DnD1 + wn01 * Dn61) +
                  Cn1 * (wn10 * DnD1 + wn11 * Dn61);
    }
    __syncthreads();

    // ---- combine + write (threads 0..63) ----------------------------------
    if (tid < 64) {
        int sim2  = blockIdx.x * 64 + tid;
        int ch2   = sim2 & 3;
        int cell2 = sim2 >> 2;
        int cc2   = cell2 % 30;
        int rc2   = cell2 / 30;
        int rr2   = rc2 % 30;
        const float* kk2 = k + ch2 * KW;

        float dz = sA0[tid] - sA1[tid];
        float z  = sB0[tid] * dz +
                   sB1[tid] * (kk2[28] * dz + kk2[30] * sAr[tid] - kk2[29] * sAi[tid]);
        bool interior = (rr2 >= 1 && rr2 <= 28 && cc2 >= 1 && cc2 <= 28);
        out[sim2] = interior ? (z + 1.0f) * 0.5f : 0.0f;
    }
}

extern "C" void kernel_launch(void* const* d_in, const int* in_sizes, int n_in,
                              void* d_out, int out_size) {
    const float* x  = (const float*)d_in[0];
    const float* qp = (const float*)d_in[1];
    if (n_in >= 2 && in_sizes[0] == 64) {
        const float* tp = x; x = qp; qp = tp;
    }
    float* out = (float*)d_out;

    fused_kernel<<<450, 128>>>(x, qp, out);
}